// round 2
// baseline (speedup 1.0000x reference)
#include <cuda_runtime.h>
#include <math.h>

#define NVARS    4000
#define NLITS    8000
#define NCLAUSES 16800
#define NEDGES   50400
#define FMAPS    256

// ---------------- device scratch (allocation-free) ----------------
__device__ float g_lh  [NLITS   * FMAPS];
__device__ float g_lc  [NLITS   * FMAPS];
__device__ float g_ch  [NCLAUSES* FMAPS];
__device__ float g_cc  [NCLAUSES* FMAPS];
__device__ float g_h1  [NCLAUSES* FMAPS];   // MLP scratch (max rows)
__device__ float g_h2  [NCLAUSES* FMAPS];
__device__ float g_cmsg[NCLAUSES* FMAPS];   // lc_msgs
__device__ float g_lmsg[NLITS   * FMAPS];   // cl_msgs
__device__ float g_flip[NLITS   * FMAPS];
__device__ float g_z   [NCLAUSES* 4 * FMAPS]; // LSTM preactivations (reused)
__device__ float g_vbuf[NVARS * 2 * FMAPS];
__device__ float g_vh1 [NVARS * 2 * FMAPS];
__device__ float g_vh2 [NVARS * 2 * FMAPS];
__device__ float g_logits[NVARS];
__device__ float g_loss[1];
__device__ int   g_litidx[NEDGES];
__device__ int   g_varidx[NEDGES];
__device__ float g_sign [NEDGES];

// ---------------- SGEMM: C[M,N] = A[M,K] @ B[K,N] (+bias)(+acc)(+relu) ----
// flags: 1=add bias, 2=relu, 4=accumulate into existing C
__global__ void sgemm64(const float* __restrict__ A, const float* __restrict__ B,
                        const float* __restrict__ bias, float* __restrict__ C,
                        int M, int N, int K, int flags)
{
    __shared__ float As[16][64];
    __shared__ float Bs[16][64];
    int tid = threadIdx.x;            // 256 threads
    int bm  = blockIdx.y * 64;
    int bn  = blockIdx.x * 64;
    int arow = tid >> 2;              // 0..63
    int acol = (tid & 3) << 2;        // 0,4,8,12
    int brow = tid >> 4;              // 0..15
    int bcol = (tid & 15) << 2;       // 0..60
    int tx = tid & 15, ty = tid >> 4;

    float acc[4][4];
#pragma unroll
    for (int i = 0; i < 4; i++)
#pragma unroll
        for (int j = 0; j < 4; j++) acc[i][j] = 0.f;

    for (int k0 = 0; k0 < K; k0 += 16) {
        float4 av = make_float4(0.f, 0.f, 0.f, 0.f);
        if (bm + arow < M)
            av = *(const float4*)(A + (size_t)(bm + arow) * K + k0 + acol);
        As[acol + 0][arow] = av.x;
        As[acol + 1][arow] = av.y;
        As[acol + 2][arow] = av.z;
        As[acol + 3][arow] = av.w;

        float4 bv = make_float4(0.f, 0.f, 0.f, 0.f);
        if (bn + bcol < N)
            bv = *(const float4*)(B + (size_t)(k0 + brow) * N + bn + bcol);
        *(float4*)&Bs[brow][bcol] = bv;
        __syncthreads();

#pragma unroll
        for (int k = 0; k < 16; k++) {
            float4 a4 = *(float4*)&As[k][ty << 2];
            float4 b4 = *(float4*)&Bs[k][tx << 2];
            float a[4] = {a4.x, a4.y, a4.z, a4.w};
            float b[4] = {b4.x, b4.y, b4.z, b4.w};
#pragma unroll
            for (int i = 0; i < 4; i++)
#pragma unroll
                for (int j = 0; j < 4; j++) acc[i][j] += a[i] * b[j];
        }
        __syncthreads();
    }

#pragma unroll
    for (int i = 0; i < 4; i++) {
        int row = bm + (ty << 2) + i;
        if (row >= M) continue;
#pragma unroll
        for (int j = 0; j < 4; j++) {
            int col = bn + (tx << 2) + j;
            if (col >= N) continue;
            float v = acc[i][j];
            if (flags & 1) v += bias[col];
            if (flags & 4) v += C[(size_t)row * N + col];
            if (flags & 2) v = fmaxf(v, 0.f);
            C[(size_t)row * N + col] = v;
        }
    }
}

// ---------------- elementwise / graph kernels ----------------
__global__ void k_build_edges(const int* __restrict__ lits,
                              int* litidx, int* varidx, float* sign)
{
    int e = blockIdx.x * blockDim.x + threadIdx.x;
    if (e >= NEDGES) return;
    int l = lits[e];
    int v = (l > 0 ? l : -l) - 1;
    varidx[e] = v;
    litidx[e] = (l > 0) ? v : (NVARS + v);
    sign[e]   = (l > 0) ? 1.f : -1.f;
}

__global__ void k_bcast_init(float* h, float* c, const float* __restrict__ init, int rows)
{
    int i = blockIdx.x * blockDim.x + threadIdx.x;
    if (i >= rows * FMAPS) return;
    h[i] = init[i & (FMAPS - 1)] * 0.0625f;   // 1/sqrt(256)
    c[i] = 0.f;
}

__global__ void k_zero(float* p, int n)
{
    int i = blockIdx.x * blockDim.x + threadIdx.x;
    if (i < n) p[i] = 0.f;
}

// lc_msgs[c] = sum over 3 literals of lc_pre[lit]
__global__ void k_gather_clause(const float* __restrict__ pre,
                                const int* __restrict__ litidx,
                                float* __restrict__ msgs)
{
    int idx = blockIdx.x * blockDim.x + threadIdx.x;
    if (idx >= NCLAUSES * FMAPS) return;
    int c = idx >> 8, f = idx & 255;
    int e = c * 3;
    float s = pre[(size_t)litidx[e]     * FMAPS + f]
            + pre[(size_t)litidx[e + 1] * FMAPS + f]
            + pre[(size_t)litidx[e + 2] * FMAPS + f];
    msgs[idx] = s;
}

// cl_msgs[lit] += cl_pre[clause]
__global__ void k_scatter_lit(const float* __restrict__ pre,
                              const int* __restrict__ litidx,
                              float* __restrict__ msgs)
{
    int idx = blockIdx.x * blockDim.x + threadIdx.x;
    if (idx >= NEDGES * FMAPS) return;
    int e = idx >> 8, f = idx & 255;
    int c = e / 3;
    atomicAdd(&msgs[(size_t)litidx[e] * FMAPS + f], pre[(size_t)c * FMAPS + f]);
}

__device__ __forceinline__ float sigf(float x) { return 1.f / (1.f + expf(-x)); }

__global__ void k_lstm_update(const float* __restrict__ z,
                              float* __restrict__ h, float* __restrict__ c, int rows)
{
    int idx = blockIdx.x * blockDim.x + threadIdx.x;
    if (idx >= rows * FMAPS) return;
    int r = idx >> 8, f = idx & 255;
    const float* zr = z + (size_t)r * (4 * FMAPS);
    float gi = zr[f], gf = zr[FMAPS + f], gg = zr[2 * FMAPS + f], go = zr[3 * FMAPS + f];
    float cn = sigf(gf) * c[idx] + sigf(gi) * tanhf(gg);
    c[idx] = cn;
    h[idx] = sigf(go) * tanhf(cn);
}

// flipped[r] = l_h[(r + NVARS) % NLITS]
__global__ void k_flip(const float* __restrict__ lh, float* __restrict__ flip)
{
    int idx = blockIdx.x * blockDim.x + threadIdx.x;
    if (idx >= NLITS * FMAPS) return;
    int r = idx >> 8, f = idx & 255;
    int src = (r < NVARS) ? (r + NVARS) : (r - NVARS);
    flip[idx] = lh[(size_t)src * FMAPS + f];
}

// vbuf[v] = concat(l_h[v], l_h[NVARS+v])
__global__ void k_vbuf(const float* __restrict__ lh, float* __restrict__ vbuf)
{
    int idx = blockIdx.x * blockDim.x + threadIdx.x;
    if (idx >= NVARS * 2 * FMAPS) return;
    int v = idx >> 9, f = idx & 511;
    float val = (f < FMAPS) ? lh[(size_t)v * FMAPS + f]
                            : lh[(size_t)(NVARS + v) * FMAPS + (f - FMAPS)];
    vbuf[idx] = val;
}

// logits[v] = dot(vh2[v], W2) + b2
__global__ void k_vote_out(const float* __restrict__ H, const float* __restrict__ W2,
                           const float* __restrict__ b2, float* __restrict__ logits)
{
    int warp = (blockIdx.x * blockDim.x + threadIdx.x) >> 5;
    int lane = threadIdx.x & 31;
    if (warp >= NVARS) return;
    const float* h = H + (size_t)warp * (2 * FMAPS);
    float s = 0.f;
#pragma unroll
    for (int k = lane; k < 2 * FMAPS; k += 32) s += h[k] * W2[k];
#pragma unroll
    for (int o = 16; o; o >>= 1) s += __shfl_down_sync(0xffffffffu, s, o);
    if (lane == 0) logits[warp] = s + b2[0];
}

__device__ __forceinline__ float softplusf(float x)
{
    return fmaxf(x, 0.f) + log1pf(expf(-fabsf(x)));
}

__global__ void k_loss(const float* __restrict__ logits,
                       const int* __restrict__ varidx,
                       const float* __restrict__ sign,
                       float* __restrict__ loss)
{
    __shared__ float red[256];
    int c = blockIdx.x * blockDim.x + threadIdx.x;
    float t = 0.f;
    if (c < NCLAUSES) {
        float s = 0.f;
#pragma unroll
        for (int k = 0; k < 3; k++) {
            int e = c * 3 + k;
            s += softplusf(logits[varidx[e]] * sign[e]);
        }
        float cv = expf(-s);
        float v = -logf(1.f - cv + 1e-8f);
        t = v * v;
    }
    red[threadIdx.x] = t;
    __syncthreads();
    for (int o = 128; o; o >>= 1) {
        if (threadIdx.x < o) red[threadIdx.x] += red[threadIdx.x + o];
        __syncthreads();
    }
    if (threadIdx.x == 0) atomicAdd(loss, red[0]);
}

__global__ void k_writeout(const float* __restrict__ logits,
                           const float* __restrict__ loss,
                           float* __restrict__ out, int out_size)
{
    int i = blockIdx.x * blockDim.x + threadIdx.x;
    if (i < NVARS && i < out_size) out[i] = logits[i];
    if (i == NVARS && out_size > NVARS) out[NVARS] = loss[0] / 32.0f;
}

// ---------------- host orchestration ----------------
static inline void gemm(const float* A, const float* B, const float* bias, float* C,
                        int M, int N, int K, int flags)
{
    dim3 g((N + 63) / 64, (M + 63) / 64);
    sgemm64<<<g, 256>>>(A, B, bias, C, M, N, K, flags);
}

static inline int gdiv(int a, int b) { return (a + b - 1) / b; }

extern "C" void kernel_launch(void* const* d_in, const int* in_sizes, int n_in,
                              void* d_out, int out_size)
{
    // Input parsing: index 1 may be the scalar n_vars; skip it if present.
    int p = 1;
    if (n_in > 1 && in_sizes[1] == 1) p = 2;
    const int*   clause_lits = (const int*)d_in[0];
    const float* L_init = (const float*)d_in[p + 0];
    const float* C_init = (const float*)d_in[p + 1];
    const float* LC_W0  = (const float*)d_in[p + 2];
    const float* LC_b0  = (const float*)d_in[p + 3];
    const float* LC_W1  = (const float*)d_in[p + 4];
    const float* LC_b1  = (const float*)d_in[p + 5];
    const float* LC_W2  = (const float*)d_in[p + 6];
    const float* LC_b2  = (const float*)d_in[p + 7];
    const float* CL_W0  = (const float*)d_in[p + 8];
    const float* CL_b0  = (const float*)d_in[p + 9];
    const float* CL_W1  = (const float*)d_in[p + 10];
    const float* CL_b1  = (const float*)d_in[p + 11];
    const float* CL_W2  = (const float*)d_in[p + 12];
    const float* CL_b2  = (const float*)d_in[p + 13];
    const float* C_Wx   = (const float*)d_in[p + 14];
    const float* C_Wh   = (const float*)d_in[p + 15];
    const float* C_b    = (const float*)d_in[p + 16];
    const float* L_Wx   = (const float*)d_in[p + 17];
    const float* L_Wh   = (const float*)d_in[p + 18];
    const float* L_b    = (const float*)d_in[p + 19];
    const float* V_W0   = (const float*)d_in[p + 20];
    const float* V_b0   = (const float*)d_in[p + 21];
    const float* V_W1   = (const float*)d_in[p + 22];
    const float* V_b1   = (const float*)d_in[p + 23];
    const float* V_W2   = (const float*)d_in[p + 24];
    const float* V_b2   = (const float*)d_in[p + 25];
    float* out = (float*)d_out;

    // Resolve device-global scratch
    float *lh, *lc, *ch, *cc, *h1, *h2, *cmsg, *lmsg, *flip, *z, *vbuf, *vh1, *vh2, *logits, *loss, *sign;
    int *litidx, *varidx;
    cudaGetSymbolAddress((void**)&lh,   g_lh);
    cudaGetSymbolAddress((void**)&lc,   g_lc);
    cudaGetSymbolAddress((void**)&ch,   g_ch);
    cudaGetSymbolAddress((void**)&cc,   g_cc);
    cudaGetSymbolAddress((void**)&h1,   g_h1);
    cudaGetSymbolAddress((void**)&h2,   g_h2);
    cudaGetSymbolAddress((void**)&cmsg, g_cmsg);
    cudaGetSymbolAddress((void**)&lmsg, g_lmsg);
    cudaGetSymbolAddress((void**)&flip, g_flip);
    cudaGetSymbolAddress((void**)&z,    g_z);
    cudaGetSymbolAddress((void**)&vbuf, g_vbuf);
    cudaGetSymbolAddress((void**)&vh1,  g_vh1);
    cudaGetSymbolAddress((void**)&vh2,  g_vh2);
    cudaGetSymbolAddress((void**)&logits, g_logits);
    cudaGetSymbolAddress((void**)&loss, g_loss);
    cudaGetSymbolAddress((void**)&sign, g_sign);
    cudaGetSymbolAddress((void**)&litidx, g_litidx);
    cudaGetSymbolAddress((void**)&varidx, g_varidx);

    const float* L_Wx_top = L_Wx;                   // rows [0,256)   -> cl_msgs part
    const float* L_Wx_bot = L_Wx + 256 * 1024;      // rows [256,512) -> flipped part

    // ---- setup ----
    k_build_edges<<<gdiv(NEDGES, 256), 256>>>(clause_lits, litidx, varidx, sign);
    k_bcast_init<<<gdiv(NLITS * FMAPS, 256), 256>>>(lh, lc, L_init, NLITS);
    k_bcast_init<<<gdiv(NCLAUSES * FMAPS, 256), 256>>>(ch, cc, C_init, NCLAUSES);
    k_zero<<<1, 32>>>(loss, 1);

    // ---- 32 message-passing rounds ----
    for (int r = 0; r < 32; r++) {
        // literal MLP3 -> lc_pre (in h1)
        gemm(lh, LC_W0, LC_b0, h1, NLITS, FMAPS, FMAPS, 1 | 2);
        gemm(h1, LC_W1, LC_b1, h2, NLITS, FMAPS, FMAPS, 1 | 2);
        gemm(h2, LC_W2, LC_b2, h1, NLITS, FMAPS, FMAPS, 1);
        // gather literal messages into clauses
        k_gather_clause<<<gdiv(NCLAUSES * FMAPS, 256), 256>>>(h1, litidx, cmsg);
        // clause LSTM
        gemm(cmsg, C_Wx, C_b, z, NCLAUSES, 4 * FMAPS, FMAPS, 1);
        gemm(ch,   C_Wh, 0,   z, NCLAUSES, 4 * FMAPS, FMAPS, 4);
        k_lstm_update<<<gdiv(NCLAUSES * FMAPS, 256), 256>>>(z, ch, cc, NCLAUSES);
        // clause MLP3 -> cl_pre (in h1)
        gemm(ch, CL_W0, CL_b0, h1, NCLAUSES, FMAPS, FMAPS, 1 | 2);
        gemm(h1, CL_W1, CL_b1, h2, NCLAUSES, FMAPS, FMAPS, 1 | 2);
        gemm(h2, CL_W2, CL_b2, h1, NCLAUSES, FMAPS, FMAPS, 1);
        // scatter clause messages into literals
        k_zero<<<gdiv(NLITS * FMAPS, 256), 256>>>(lmsg, NLITS * FMAPS);
        k_scatter_lit<<<gdiv(NEDGES * FMAPS, 256), 256>>>(h1, litidx, lmsg);
        // literal LSTM: x = [cl_msgs, flipped]
        k_flip<<<gdiv(NLITS * FMAPS, 256), 256>>>(lh, flip);
        gemm(lmsg, L_Wx_top, L_b, z, NLITS, 4 * FMAPS, FMAPS, 1);
        gemm(flip, L_Wx_bot, 0,   z, NLITS, 4 * FMAPS, FMAPS, 4);
        gemm(lh,   L_Wh,     0,   z, NLITS, 4 * FMAPS, FMAPS, 4);
        k_lstm_update<<<gdiv(NLITS * FMAPS, 256), 256>>>(z, lh, lc, NLITS);
        // vote + clause loss
        k_vbuf<<<gdiv(NVARS * 2 * FMAPS, 256), 256>>>(lh, vbuf);
        gemm(vbuf, V_W0, V_b0, vh1, NVARS, 2 * FMAPS, 2 * FMAPS, 1 | 2);
        gemm(vh1,  V_W1, V_b1, vh2, NVARS, 2 * FMAPS, 2 * FMAPS, 1 | 2);
        k_vote_out<<<gdiv(NVARS * 32, 256), 256>>>(vh2, V_W2, V_b2, logits);
        k_loss<<<gdiv(NCLAUSES, 256), 256>>>(logits, varidx, sign, loss);
    }

    // ---- output: final logits (== round-32 vote) + loss/32 ----
    k_writeout<<<gdiv(NVARS + 1, 256), 256>>>(logits, loss, out, out_size);
}